// round 3
// baseline (speedup 1.0000x reference)
#include <cuda_runtime.h>
#include <cuda_fp16.h>

// pri scratch: [t_global (1152)][b (64)][n*16+d (512)] fp16 = 75.5 MB (fits L2)
static __device__ __half g_pri[37748736];

union F2U { unsigned long long u; float2 f; };
union H2U { __half2 h; unsigned u; };

__device__ __forceinline__ unsigned long long pk2(float lo, float hi){
    unsigned long long r; asm("mov.b64 %0, {%1,%2};" : "=l"(r) : "f"(lo), "f"(hi)); return r;
}
__device__ __forceinline__ unsigned long long ffma2(unsigned long long a,
                                                    unsigned long long b,
                                                    unsigned long long c){
    unsigned long long d;
    asm("fma.rn.f32x2 %0, %1, %2, %3;" : "=l"(d) : "l"(a), "l"(b), "l"(c));
    return d;
}

// ---------------------------------------------------------------------------
// Kernel 1: pri[b,t,n,d] = sum_j x[b,t,j] * W[t,n,j,d]
// One CTA per global t (1152 CTAs, 512 threads).
// Thread tile: 8 b-rows x 8 d-columns (one n, half of d) using packed f32x2 FMA.
// ---------------------------------------------------------------------------
__global__ __launch_bounds__(512) void k_pri(
    const float* __restrict__ xT, const float* __restrict__ xA,
    const float* __restrict__ xV, const float* __restrict__ xF,
    const float* __restrict__ wT, const float* __restrict__ wA,
    const float* __restrict__ wV, const float* __restrict__ wF)
{
    int tg = blockIdx.x;
    const float* x; const float* w; int T, t;
    if (tg < 128)      { x = xT; w = wT; T = 128; t = tg;       }
    else if (tg < 640) { x = xA; w = wA; T = 512; t = tg - 128; }
    else if (tg < 896) { x = xV; w = wV; T = 256; t = tg - 640; }
    else               { x = xF; w = wF; T = 256; t = tg - 896; }

    __shared__ float xs[64][65];            // transposed x_t: xs[j][b]
    int tid = threadIdx.x;
    #pragma unroll
    for (int idx = tid; idx < 4096; idx += 512) {
        int b = idx >> 6, j = idx & 63;
        xs[j][b] = x[((size_t)b * T + t) * 64 + j];
    }
    __syncthreads();

    const float* wt = w + (size_t)t * 32768;       // W_t: [n][j][d]
    int ctile = tid & 63;                          // 64 column tiles of 8
    int n  = ctile >> 1;
    int d0 = (ctile & 1) << 3;
    int b0 = (tid >> 6) << 3;                      // 8 row tiles of 8
    const float* wp = wt + n * 1024 + d0;

    unsigned long long acc[8][4];
    #pragma unroll
    for (int r = 0; r < 8; r++)
        #pragma unroll
        for (int c = 0; c < 4; c++) acc[r][c] = 0ull;

    #pragma unroll 4
    for (int j = 0; j < 64; j++) {
        float4 w0 = __ldg((const float4*)(wp + j * 16));
        float4 w1 = __ldg((const float4*)(wp + j * 16 + 4));
        unsigned long long bw0 = pk2(w0.x, w0.y);
        unsigned long long bw1 = pk2(w0.z, w0.w);
        unsigned long long bw2 = pk2(w1.x, w1.y);
        unsigned long long bw3 = pk2(w1.z, w1.w);
        #pragma unroll
        for (int r = 0; r < 8; r++) {
            float a = xs[j][b0 + r];               // warp-broadcast, conflict-free
            unsigned long long av = pk2(a, a);
            acc[r][0] = ffma2(av, bw0, acc[r][0]);
            acc[r][1] = ffma2(av, bw1, acc[r][1]);
            acc[r][2] = ffma2(av, bw2, acc[r][2]);
            acc[r][3] = ffma2(av, bw3, acc[r][3]);
        }
    }

    #pragma unroll
    for (int r = 0; r < 8; r++) {
        uint4 st;
        unsigned* su = &st.x;
        #pragma unroll
        for (int c = 0; c < 4; c++) {
            F2U v; v.u = acc[r][c];
            H2U h; h.h = __floats2half2_rn(v.f.x, v.f.y);
            su[c] = h.u;
        }
        __half* dst = g_pri + ((size_t)(tg * 64 + b0 + r)) * 512 + (ctile << 3);
        *reinterpret_cast<uint4*>(dst) = st;       // 16B aligned
    }
}

// ---------------------------------------------------------------------------
// Kernel 2: fused dynamic routing (3 iterations + final), one CTA per (m, b).
// 16 warps; warp w owns t in {w, w+16, ...}; lane = vertex n; v,s in registers.
// Pass 0: v1 = tanh(sum_t pri / 32)  (softmax of zeros is exactly uniform)
// Pass k: beta[t] += v.pri[t]; rc = softmax_n(beta[t]); s += rc*pri[t]; v=tanh(s)
// ---------------------------------------------------------------------------
__device__ __forceinline__ void h8f(uint4 u, float* pf){
    __half2* h = reinterpret_cast<__half2*>(&u);
    #pragma unroll
    for (int k = 0; k < 4; k++) {
        float2 f = __half22float2(h[k]);
        pf[2*k] = f.x; pf[2*k+1] = f.y;
    }
}

template<int NT>
__device__ __forceinline__ void route_body(int b, int t0, float* __restrict__ outm,
                                           float (*red)[512], float* vsm)
{
    int tid  = threadIdx.x;
    int w    = tid >> 5;
    int lane = tid & 31;

    float beta[NT];
    #pragma unroll 1
    for (int i = 0; i < NT; i++) beta[i] = 0.f;
    float v[16];

    // ---- pass 0: uniform routing coefficients ----
    {
        float s[16];
        #pragma unroll
        for (int d = 0; d < 16; d++) s[d] = 0.f;
        #pragma unroll 1
        for (int i = 0; i < NT; i++) {
            int t = w + (i << 4);
            const __half* pp = g_pri + (((size_t)((t0 + t) * 64 + b)) << 9) + (lane << 4);
            uint4 u0 = __ldg((const uint4*)pp);
            uint4 u1 = __ldg((const uint4*)(pp + 8));
            float pf[16]; h8f(u0, pf); h8f(u1, pf + 8);
            #pragma unroll
            for (int d = 0; d < 16; d++) s[d] += pf[d];
        }
        #pragma unroll
        for (int d = 0; d < 16; d++) red[w][(lane << 4) + d] = s[d];
        __syncthreads();
        float tot = 0.f;
        #pragma unroll
        for (int ww = 0; ww < 16; ww++) tot += red[ww][tid];
        vsm[(tid >> 4) * 17 + (tid & 15)] = tanhf(tot * (1.0f / 32.0f));
        __syncthreads();
        #pragma unroll
        for (int d = 0; d < 16; d++) v[d] = vsm[lane * 17 + d];
    }

    // ---- 3 routing iterations (last one produces the output) ----
    #pragma unroll 1
    for (int it = 0; it < 3; it++) {
        float s[16];
        #pragma unroll
        for (int d = 0; d < 16; d++) s[d] = 0.f;
        #pragma unroll 1
        for (int i = 0; i < NT; i++) {
            int t = w + (i << 4);
            const __half* pp = g_pri + (((size_t)((t0 + t) * 64 + b)) << 9) + (lane << 4);
            uint4 u0 = __ldg((const uint4*)pp);
            uint4 u1 = __ldg((const uint4*)(pp + 8));
            float pf[16]; h8f(u0, pf); h8f(u1, pf + 8);

            float delta = 0.f;
            #pragma unroll
            for (int d = 0; d < 16; d++) delta = fmaf(v[d], pf[d], delta);
            float bt = beta[i] + delta;
            beta[i] = bt;

            // softmax over n (lanes)
            float mx = bt;
            #pragma unroll
            for (int off = 16; off > 0; off >>= 1)
                mx = fmaxf(mx, __shfl_xor_sync(0xffffffffu, mx, off));
            float e = __expf(bt - mx);
            float Z = e;
            #pragma unroll
            for (int off = 16; off > 0; off >>= 1)
                Z += __shfl_xor_sync(0xffffffffu, Z, off);
            float rc = e / Z;

            #pragma unroll
            for (int d = 0; d < 16; d++) s[d] = fmaf(rc, pf[d], s[d]);
        }
        #pragma unroll
        for (int d = 0; d < 16; d++) red[w][(lane << 4) + d] = s[d];
        __syncthreads();
        float tot = 0.f;
        #pragma unroll
        for (int ww = 0; ww < 16; ww++) tot += red[ww][tid];
        if (it == 2) {
            outm[(b << 9) + tid] = tanhf(tot);
        } else {
            vsm[(tid >> 4) * 17 + (tid & 15)] = tanhf(tot);
            __syncthreads();
            #pragma unroll
            for (int d = 0; d < 16; d++) v[d] = vsm[lane * 17 + d];
        }
    }
}

__global__ __launch_bounds__(512) void k_route(float* __restrict__ out)
{
    __shared__ float red[16][512];
    __shared__ float vsm[32 * 17];
    int m = blockIdx.x >> 6;
    int b = blockIdx.x & 63;
    if      (m == 0) route_body<8 >(b,   0, out,          red, vsm);
    else if (m == 1) route_body<32>(b, 128, out + 32768,  red, vsm);
    else if (m == 2) route_body<16>(b, 640, out + 65536,  red, vsm);
    else             route_body<16>(b, 896, out + 98304,  red, vsm);
}

extern "C" void kernel_launch(void* const* d_in, const int* in_sizes, int n_in,
                              void* d_out, int out_size)
{
    const float* xT = (const float*)d_in[0];
    const float* xA = (const float*)d_in[1];
    const float* xV = (const float*)d_in[2];
    const float* xF = (const float*)d_in[3];
    const float* wT = (const float*)d_in[4];
    const float* wA = (const float*)d_in[5];
    const float* wV = (const float*)d_in[6];
    const float* wF = (const float*)d_in[7];

    k_pri  <<<1152, 512>>>(xT, xA, xV, xF, wT, wA, wV, wF);
    k_route<<<256, 512>>>((float*)d_out);
}

// round 5
// speedup vs baseline: 2.8361x; 2.8361x over previous
#include <cuda_runtime.h>
#include <cuda_fp16.h>
#include <cuda_bf16.h>

// pri scratch: [t_global (1152)][b (64)][n*16+d (512)] fp16 = 75.5 MB (L2-resident)
static __device__ __half g_pri[37748736];

// ---------------------------------------------------------------------------
// Kernel 1: pri[b,t,n,d] = sum_j x[b,t,j] * W[t,n,j,d]  via bf16 split MMA.
// One CTA per global t (1152 CTAs, 512 threads = 16 warps).
// A = x_t [64b x 64j], B = W_t viewed as [64j x 512(nd)], C = [64b x 512nd].
// fp32 operands split into bf16 hi/lo; D += Ah*Bh + Ah*Bl + Al*Bh (fp32 acc).
// ---------------------------------------------------------------------------
#define SA 68    // A smem row stride (bf16 elems)
#define SB 68    // B smem row stride (bf16 elems)
#define SC 520   // C smem row stride (fp16 elems)
#define K_PRI_SMEM 156672

__device__ __forceinline__ void mma16816(float* c, const unsigned* a,
                                         unsigned b0, unsigned b1) {
    asm volatile(
        "mma.sync.aligned.m16n8k16.row.col.f32.bf16.bf16.f32 "
        "{%0,%1,%2,%3}, {%4,%5,%6,%7}, {%8,%9}, {%0,%1,%2,%3};"
        : "+f"(c[0]), "+f"(c[1]), "+f"(c[2]), "+f"(c[3])
        : "r"(a[0]), "r"(a[1]), "r"(a[2]), "r"(a[3]), "r"(b0), "r"(b1));
}

__global__ __launch_bounds__(512, 1) void k_pri(
    const float* __restrict__ xT, const float* __restrict__ xA,
    const float* __restrict__ xV, const float* __restrict__ xF,
    const float* __restrict__ wT, const float* __restrict__ wA,
    const float* __restrict__ wV, const float* __restrict__ wF)
{
    extern __shared__ __nv_bfloat16 sm[];
    __nv_bfloat16* Ah = sm;                  // 64 x SA
    __nv_bfloat16* Al = Ah + 64 * SA;
    __nv_bfloat16* Bh = Al + 64 * SA;        // 512 x SB
    __nv_bfloat16* Bl = Bh + 512 * SB;
    __half* Cs = reinterpret_cast<__half*>(Bh);   // reused after MMA

    int tg_blk = blockIdx.x;
    const float* x; const float* w; int T, t;
    if (tg_blk < 128)      { x = xT; w = wT; T = 128; t = tg_blk;       }
    else if (tg_blk < 640) { x = xA; w = wA; T = 512; t = tg_blk - 128; }
    else if (tg_blk < 896) { x = xV; w = wV; T = 256; t = tg_blk - 640; }
    else                   { x = xF; w = wF; T = 256; t = tg_blk - 896; }

    int tid = threadIdx.x;

    // ---- stage x_t -> Ah/Al [b][j] ----
    #pragma unroll
    for (int idx = tid; idx < 4096; idx += 512) {
        int b = idx >> 6, j = idx & 63;
        float v = x[((size_t)b * T + t) * 64 + j];
        __nv_bfloat16 h = __float2bfloat16_rn(v);
        Ah[b * SA + j] = h;
        Al[b * SA + j] = __float2bfloat16_rn(v - __bfloat162float(h));
    }

    // ---- stage W_t -> Bh/Bl [nd][j] ----
    const float4* w4 = reinterpret_cast<const float4*>(w + (size_t)t * 32768);
    #pragma unroll
    for (int f = tid; f < 8192; f += 512) {
        int d0 = (f & 3) << 2;
        int j  = (f >> 2) & 63;
        int n  = f >> 8;
        float4 v = __ldg(w4 + f);
        float vv[4] = {v.x, v.y, v.z, v.w};
        #pragma unroll
        for (int q = 0; q < 4; q++) {
            int nd = (n << 4) + d0 + q;
            __nv_bfloat16 h = __float2bfloat16_rn(vv[q]);
            Bh[nd * SB + j] = h;
            Bl[nd * SB + j] = __float2bfloat16_rn(vv[q] - __bfloat162float(h));
        }
    }
    __syncthreads();

    // ---- MMA: warp = (m-pair) x (nd-octet) ----
    int lane = tid & 31, wrp = tid >> 5;
    int g  = lane >> 2;          // groupID
    int tq = lane & 3;           // threadID_in_group
    int mbase  = (wrp & 1) * 32;
    int ndbase = (wrp >> 1) * 64;

    float acc[2][8][4];
    #pragma unroll
    for (int mt = 0; mt < 2; mt++)
        #pragma unroll
        for (int nt = 0; nt < 8; nt++)
            #pragma unroll
            for (int q = 0; q < 4; q++) acc[mt][nt][q] = 0.f;

    #pragma unroll
    for (int k0 = 0; k0 < 64; k0 += 16) {
        unsigned ah[2][4], al[2][4];
        #pragma unroll
        for (int mt = 0; mt < 2; mt++) {
            int r0 = mbase + mt * 16 + g;
            int kc = k0 + tq * 2;
            ah[mt][0] = *(const unsigned*)&Ah[r0 * SA + kc];
            ah[mt][1] = *(const unsigned*)&Ah[(r0 + 8) * SA + kc];
            ah[mt][2] = *(const unsigned*)&Ah[r0 * SA + kc + 8];
            ah[mt][3] = *(const unsigned*)&Ah[(r0 + 8) * SA + kc + 8];
            al[mt][0] = *(const unsigned*)&Al[r0 * SA + kc];
            al[mt][1] = *(const unsigned*)&Al[(r0 + 8) * SA + kc];
            al[mt][2] = *(const unsigned*)&Al[r0 * SA + kc + 8];
            al[mt][3] = *(const unsigned*)&Al[(r0 + 8) * SA + kc + 8];
        }
        #pragma unroll
        for (int nt = 0; nt < 8; nt++) {
            int col = ndbase + nt * 8 + g;
            int kc  = k0 + tq * 2;
            unsigned bh0 = *(const unsigned*)&Bh[col * SB + kc];
            unsigned bh1 = *(const unsigned*)&Bh[col * SB + kc + 8];
            unsigned bl0 = *(const unsigned*)&Bl[col * SB + kc];
            unsigned bl1 = *(const unsigned*)&Bl[col * SB + kc + 8];
            #pragma unroll
            for (int mt = 0; mt < 2; mt++) {
                mma16816(acc[mt][nt], ah[mt], bh0, bh1);
                mma16816(acc[mt][nt], ah[mt], bl0, bl1);
                mma16816(acc[mt][nt], al[mt], bh0, bh1);
            }
        }
    }
    __syncthreads();   // B smem no longer needed; reuse as Cs

    // ---- epilogue: C frags -> Cs (fp16), then coalesced copy to g_pri ----
    #pragma unroll
    for (int mt = 0; mt < 2; mt++)
        #pragma unroll
        for (int nt = 0; nt < 8; nt++) {
            int r0 = mbase + mt * 16 + g;
            int c0 = ndbase + nt * 8 + tq * 2;
            __half2 lo = __floats2half2_rn(acc[mt][nt][0], acc[mt][nt][1]);
            __half2 hi = __floats2half2_rn(acc[mt][nt][2], acc[mt][nt][3]);
            *(__half2*)&Cs[r0 * SC + c0]       = lo;
            *(__half2*)&Cs[(r0 + 8) * SC + c0] = hi;
        }
    __syncthreads();

    uint4* dst = reinterpret_cast<uint4*>(g_pri + (size_t)tg_blk * 64 * 512);
    #pragma unroll
    for (int i = tid; i < 4096; i += 512) {
        int b = i >> 6, off = i & 63;
        dst[b * 64 + off] = *(const uint4*)&Cs[b * SC + off * 8];
    }
}

// ---------------------------------------------------------------------------
// Kernel 2: fused dynamic routing. One CTA per (m, b); 16 warps; lane = vertex.
// 2-way t-interleave for ILP; no max-subtract (beta is tiny); beta in regs.
// ---------------------------------------------------------------------------
__device__ __forceinline__ void h8f(uint4 u, float* pf) {
    __half2* h = reinterpret_cast<__half2*>(&u);
    #pragma unroll
    for (int k = 0; k < 4; k++) {
        float2 f = __half22float2(h[k]);
        pf[2 * k] = f.x; pf[2 * k + 1] = f.y;
    }
}

__device__ __forceinline__ void load_pf(int tglob, int b, int lane, float* pf) {
    const __half* pp = g_pri + (((size_t)(tglob * 64 + b)) << 9) + (lane << 4);
    uint4 u0 = __ldg((const uint4*)pp);
    uint4 u1 = __ldg((const uint4*)(pp + 8));
    h8f(u0, pf); h8f(u1, pf + 8);
}

__device__ __forceinline__ float dot16(const float* v, const float* p) {
    float s0 = 0.f, s1 = 0.f, s2 = 0.f, s3 = 0.f;
    #pragma unroll
    for (int d = 0; d < 4; d++) {
        s0 = fmaf(v[d],      p[d],      s0);
        s1 = fmaf(v[d + 4],  p[d + 4],  s1);
        s2 = fmaf(v[d + 8],  p[d + 8],  s2);
        s3 = fmaf(v[d + 12], p[d + 12], s3);
    }
    return (s0 + s1) + (s2 + s3);
}

template<int NT>
__device__ __forceinline__ void route_body(int b, int t0, float* __restrict__ outm,
                                           float (*red)[512], float* vsm)
{
    int tid  = threadIdx.x;
    int w    = tid >> 5;
    int lane = tid & 31;

    float beta[NT];
    #pragma unroll
    for (int i = 0; i < NT; i++) beta[i] = 0.f;
    float v[16];

    // ---- pass 0: uniform routing coefficients (softmax(0) = 1/32) ----
    {
        float s[16];
        #pragma unroll
        for (int d = 0; d < 16; d++) s[d] = 0.f;
        #pragma unroll
        for (int i = 0; i < NT; i += 2) {
            float pa[16], pb[16];
            load_pf(t0 + w + (i << 4), b, lane, pa);
            load_pf(t0 + w + ((i + 1) << 4), b, lane, pb);
            #pragma unroll
            for (int d = 0; d < 16; d++) s[d] += pa[d] + pb[d];
        }
        #pragma unroll
        for (int d = 0; d < 16; d++) red[w][(lane << 4) + d] = s[d];
        __syncthreads();
        float tot = 0.f;
        #pragma unroll
        for (int ww = 0; ww < 16; ww++) tot += red[ww][tid];
        vsm[(tid >> 4) * 17 + (tid & 15)] = tanhf(tot * (1.0f / 32.0f));
        __syncthreads();
        #pragma unroll
        for (int d = 0; d < 16; d++) v[d] = vsm[lane * 17 + d];
        __syncthreads();
    }

    // ---- 3 routing iterations (last produces output) ----
    #pragma unroll 1
    for (int it = 0; it < 3; it++) {
        float s[16];
        #pragma unroll
        for (int d = 0; d < 16; d++) s[d] = 0.f;
        #pragma unroll
        for (int i = 0; i < NT; i += 2) {
            float pa[16], pb[16];
            load_pf(t0 + w + (i << 4), b, lane, pa);
            load_pf(t0 + w + ((i + 1) << 4), b, lane, pb);

            float ba = beta[i]     + dot16(v, pa);
            float bb = beta[i + 1] + dot16(v, pb);
            beta[i] = ba; beta[i + 1] = bb;

            // softmax over n (32 lanes), no max-subtract: |beta| << 10
            float ea = __expf(ba), eb = __expf(bb);
            float Za = ea, Zb = eb;
            #pragma unroll
            for (int off = 16; off > 0; off >>= 1) {
                Za += __shfl_xor_sync(0xffffffffu, Za, off);
                Zb += __shfl_xor_sync(0xffffffffu, Zb, off);
            }
            float ra = __fdividef(ea, Za);
            float rb = __fdividef(eb, Zb);
            #pragma unroll
            for (int d = 0; d < 16; d++)
                s[d] = fmaf(ra, pa[d], fmaf(rb, pb[d], s[d]));
        }
        #pragma unroll
        for (int d = 0; d < 16; d++) red[w][(lane << 4) + d] = s[d];
        __syncthreads();
        float tot = 0.f;
        #pragma unroll
        for (int ww = 0; ww < 16; ww++) tot += red[ww][tid];
        if (it == 2) {
            outm[(b << 9) + tid] = tanhf(tot);
        } else {
            vsm[(tid >> 4) * 17 + (tid & 15)] = tanhf(tot);
            __syncthreads();
            #pragma unroll
            for (int d = 0; d < 16; d++) v[d] = vsm[lane * 17 + d];
            __syncthreads();
        }
    }
}

__global__ __launch_bounds__(512) void k_route(float* __restrict__ out)
{
    __shared__ float red[16][512];
    __shared__ float vsm[32 * 17];
    int m = blockIdx.x >> 6;
    int b = blockIdx.x & 63;
    if      (m == 0) route_body<8 >(b,   0, out,          red, vsm);
    else if (m == 1) route_body<32>(b, 128, out + 32768,  red, vsm);
    else if (m == 2) route_body<16>(b, 640, out + 65536,  red, vsm);
    else             route_body<16>(b, 896, out + 98304,  red, vsm);
}

extern "C" void kernel_launch(void* const* d_in, const int* in_sizes, int n_in,
                              void* d_out, int out_size)
{
    const float* xT = (const float*)d_in[0];
    const float* xA = (const float*)d_in[1];
    const float* xV = (const float*)d_in[2];
    const float* xF = (const float*)d_in[3];
    const float* wT = (const float*)d_in[4];
    const float* wA = (const float*)d_in[5];
    const float* wV = (const float*)d_in[6];
    const float* wF = (const float*)d_in[7];

    // Unconditional (no static guard — harness contract): idempotent,
    // allocation-free, executes immediately (not a stream op / graph node).
    cudaFuncSetAttribute(k_pri, cudaFuncAttributeMaxDynamicSharedMemorySize,
                         K_PRI_SMEM);

    k_pri  <<<1152, 512, K_PRI_SMEM>>>(xT, xA, xV, xF, wT, wA, wV, wF);
    k_route<<<256, 512>>>((float*)d_out);
}

// round 8
// speedup vs baseline: 2.8682x; 1.0113x over previous
#include <cuda_runtime.h>
#include <cuda_fp16.h>
#include <cuda_bf16.h>

// pri scratch: [t_global (1152)][b (64)][n*16+d (512)] fp16 = 75.5 MB (L2-resident)
static __device__ __half g_pri[37748736];

// ---------------------------------------------------------------------------
// Kernel 1: pri[b,t,n,d] = sum_j x[b,t,j] * W[t,n,j,d]  via bf16 split MMA.
// One CTA per global t. SA/SB = 72 elems (36 words): fragment-load rows land at
// 4g mod 32 -> 8 rows x 4 words tile all banks, conflict-free.
// ---------------------------------------------------------------------------
#define SA 72
#define SB 72
#define SC 520
#define K_PRI_SMEM 165888

__device__ __forceinline__ void mma16816(float* c, const unsigned* a,
                                         unsigned b0, unsigned b1) {
    asm volatile(
        "mma.sync.aligned.m16n8k16.row.col.f32.bf16.bf16.f32 "
        "{%0,%1,%2,%3}, {%4,%5,%6,%7}, {%8,%9}, {%0,%1,%2,%3};"
        : "+f"(c[0]), "+f"(c[1]), "+f"(c[2]), "+f"(c[3])
        : "r"(a[0]), "r"(a[1]), "r"(a[2]), "r"(a[3]), "r"(b0), "r"(b1));
}

__global__ __launch_bounds__(512, 1) void k_pri(
    const float* __restrict__ xT, const float* __restrict__ xA,
    const float* __restrict__ xV, const float* __restrict__ xF,
    const float* __restrict__ wT, const float* __restrict__ wA,
    const float* __restrict__ wV, const float* __restrict__ wF)
{
    extern __shared__ __nv_bfloat16 sm[];
    __nv_bfloat16* Ah = sm;                     // 64 x SA
    __nv_bfloat16* Al = Ah + 64 * SA;
    __nv_bfloat16* Bh = Al + 64 * SA;           // 512 x SB
    __nv_bfloat16* Bl = Bh + 512 * SB;
    __half* Cs = reinterpret_cast<__half*>(Bh); // reused after MMA

    int tg_blk = blockIdx.x;
    const float* x; const float* w; int T, t;
    if (tg_blk < 128)      { x = xT; w = wT; T = 128; t = tg_blk;       }
    else if (tg_blk < 640) { x = xA; w = wA; T = 512; t = tg_blk - 128; }
    else if (tg_blk < 896) { x = xV; w = wV; T = 256; t = tg_blk - 640; }
    else                   { x = xF; w = wF; T = 256; t = tg_blk - 896; }

    int tid = threadIdx.x;

    // ---- stage x_t -> Ah/Al [b][j], paired-j bf162 stores ----
    #pragma unroll
    for (int u = tid; u < 2048; u += 512) {
        int bb = u >> 5, jp = u & 31;
        float2 v2 = *reinterpret_cast<const float2*>(
            x + ((size_t)bb * T + t) * 64 + jp * 2);
        __nv_bfloat16 h0 = __float2bfloat16_rn(v2.x);
        __nv_bfloat16 h1 = __float2bfloat16_rn(v2.y);
        __nv_bfloat162 hh; hh.x = h0; hh.y = h1;
        __nv_bfloat162 ll;
        ll.x = __float2bfloat16_rn(v2.x - __bfloat162float(h0));
        ll.y = __float2bfloat16_rn(v2.y - __bfloat162float(h1));
        *reinterpret_cast<__nv_bfloat162*>(&Ah[bb * SA + jp * 2]) = hh;
        *reinterpret_cast<__nv_bfloat162*>(&Al[bb * SA + jp * 2]) = ll;
    }

    // ---- stage W_t -> Bh/Bl [nd][j], paired-j bf162 stores ----
    const float4* w4 = reinterpret_cast<const float4*>(w + (size_t)t * 32768);
    #pragma unroll
    for (int u = tid; u < 4096; u += 512) {
        int d0c = u & 3;            // d-quad
        int jp  = (u >> 2) & 31;    // j-pair
        int n   = u >> 7;
        float4 va = __ldg(w4 + n * 256 + jp * 8 + d0c);      // j = 2jp
        float4 vb = __ldg(w4 + n * 256 + jp * 8 + 4 + d0c);  // j = 2jp+1
        float aa[4] = {va.x, va.y, va.z, va.w};
        float bb[4] = {vb.x, vb.y, vb.z, vb.w};
        #pragma unroll
        for (int q = 0; q < 4; q++) {
            int row = (n << 4) + d0c * 4 + q;
            __nv_bfloat16 ha = __float2bfloat16_rn(aa[q]);
            __nv_bfloat16 hb = __float2bfloat16_rn(bb[q]);
            __nv_bfloat162 hh; hh.x = ha; hh.y = hb;
            __nv_bfloat162 ll;
            ll.x = __float2bfloat16_rn(aa[q] - __bfloat162float(ha));
            ll.y = __float2bfloat16_rn(bb[q] - __bfloat162float(hb));
            *reinterpret_cast<__nv_bfloat162*>(&Bh[row * SB + jp * 2]) = hh;
            *reinterpret_cast<__nv_bfloat162*>(&Bl[row * SB + jp * 2]) = ll;
        }
    }
    __syncthreads();

    // ---- MMA: warp = (m-pair) x (nd-octet) ----
    int lane = tid & 31, wrp = tid >> 5;
    int g  = lane >> 2;
    int tq = lane & 3;
    int mbase  = (wrp & 1) * 32;
    int ndbase = (wrp >> 1) * 64;

    float acc[2][8][4];
    #pragma unroll
    for (int mt = 0; mt < 2; mt++)
        #pragma unroll
        for (int nt = 0; nt < 8; nt++)
            #pragma unroll
            for (int q = 0; q < 4; q++) acc[mt][nt][q] = 0.f;

    #pragma unroll
    for (int k0 = 0; k0 < 64; k0 += 16) {
        unsigned ah[2][4], al[2][4];
        #pragma unroll
        for (int mt = 0; mt < 2; mt++) {
            int r0 = mbase + mt * 16 + g;
            int kc = k0 + tq * 2;
            ah[mt][0] = *(const unsigned*)&Ah[r0 * SA + kc];
            ah[mt][1] = *(const unsigned*)&Ah[(r0 + 8) * SA + kc];
            ah[mt][2] = *(const unsigned*)&Ah[r0 * SA + kc + 8];
            ah[mt][3] = *(const unsigned*)&Ah[(r0 + 8) * SA + kc + 8];
            al[mt][0] = *(const unsigned*)&Al[r0 * SA + kc];
            al[mt][1] = *(const unsigned*)&Al[(r0 + 8) * SA + kc];
            al[mt][2] = *(const unsigned*)&Al[r0 * SA + kc + 8];
            al[mt][3] = *(const unsigned*)&Al[(r0 + 8) * SA + kc + 8];
        }
        #pragma unroll
        for (int nt = 0; nt < 8; nt++) {
            int col = ndbase + nt * 8 + g;
            int kc  = k0 + tq * 2;
            unsigned bh0 = *(const unsigned*)&Bh[col * SB + kc];
            unsigned bh1 = *(const unsigned*)&Bh[col * SB + kc + 8];
            unsigned bl0 = *(const unsigned*)&Bl[col * SB + kc];
            unsigned bl1 = *(const unsigned*)&Bl[col * SB + kc + 8];
            #pragma unroll
            for (int mt = 0; mt < 2; mt++) {
                mma16816(acc[mt][nt], ah[mt], bh0, bh1);
                mma16816(acc[mt][nt], ah[mt], bl0, bl1);
                mma16816(acc[mt][nt], al[mt], bh0, bh1);
            }
        }
    }
    __syncthreads();   // B smem no longer needed; reuse as Cs

    #pragma unroll
    for (int mt = 0; mt < 2; mt++)
        #pragma unroll
        for (int nt = 0; nt < 8; nt++) {
            int r0 = mbase + mt * 16 + g;
            int c0 = ndbase + nt * 8 + tq * 2;
            __half2 lo = __floats2half2_rn(acc[mt][nt][0], acc[mt][nt][1]);
            __half2 hi = __floats2half2_rn(acc[mt][nt][2], acc[mt][nt][3]);
            *(__half2*)&Cs[r0 * SC + c0]       = lo;
            *(__half2*)&Cs[(r0 + 8) * SC + c0] = hi;
        }
    __syncthreads();

    uint4* dst = reinterpret_cast<uint4*>(g_pri + (size_t)tg_blk * 64 * 512);
    #pragma unroll
    for (int i = tid; i < 4096; i += 512) {
        int bb = i >> 6, off = i & 63;
        dst[bb * 64 + off] = *(const uint4*)&Cs[bb * SC + off * 8];
    }
}

// ---------------------------------------------------------------------------
// Kernel 2: fused dynamic routing. One CTA per (m, b); 16 warps; lane = vertex.
// 4-way t-interleave; pri kept as raw half2 regs, lazily unpacked (fp32 math).
// ---------------------------------------------------------------------------
__device__ __forceinline__ void ld_raw(int tglob, int b, int lane,
                                       uint4& ua, uint4& ub) {
    const __half* pp = g_pri + (((size_t)(tglob * 64 + b)) << 9) + (lane << 4);
    ua = __ldg((const uint4*)pp);
    ub = __ldg((const uint4*)(pp + 8));
}

__device__ __forceinline__ float dot_raw(const float* v, uint4 ua, uint4 ub) {
    const __half2* ha = reinterpret_cast<const __half2*>(&ua);
    const __half2* hb = reinterpret_cast<const __half2*>(&ub);
    float s0 = 0.f, s1 = 0.f, s2 = 0.f, s3 = 0.f;
    #pragma unroll
    for (int k = 0; k < 4; k++) {
        float2 fa = __half22float2(ha[k]);
        float2 fb = __half22float2(hb[k]);
        s0 = fmaf(v[2 * k],     fa.x, s0);
        s1 = fmaf(v[2 * k + 1], fa.y, s1);
        s2 = fmaf(v[8 + 2 * k],     fb.x, s2);
        s3 = fmaf(v[8 + 2 * k + 1], fb.y, s3);
    }
    return (s0 + s1) + (s2 + s3);
}

__device__ __forceinline__ void s_upd(float* s, float r, uint4 ua, uint4 ub) {
    const __half2* ha = reinterpret_cast<const __half2*>(&ua);
    const __half2* hb = reinterpret_cast<const __half2*>(&ub);
    #pragma unroll
    for (int k = 0; k < 4; k++) {
        float2 fa = __half22float2(ha[k]);
        float2 fb = __half22float2(hb[k]);
        s[2 * k]         = fmaf(r, fa.x, s[2 * k]);
        s[2 * k + 1]     = fmaf(r, fa.y, s[2 * k + 1]);
        s[8 + 2 * k]     = fmaf(r, fb.x, s[8 + 2 * k]);
        s[8 + 2 * k + 1] = fmaf(r, fb.y, s[8 + 2 * k + 1]);
    }
}

template<int NT>
__device__ __forceinline__ void route_body(int b, int t0, float* __restrict__ outm,
                                           float (*red)[512], float* vsm)
{
    int tid  = threadIdx.x;
    int w    = tid >> 5;
    int lane = tid & 31;

    float beta[NT];
    #pragma unroll
    for (int i = 0; i < NT; i++) beta[i] = 0.f;
    float v[16];

    // ---- pass 0: uniform routing coefficients (softmax(0) = 1/32) ----
    {
        float s[16];
        #pragma unroll
        for (int d = 0; d < 16; d++) s[d] = 0.f;
        #pragma unroll
        for (int i = 0; i < NT; i += 4) {
            uint4 ua[4], ub[4];
            #pragma unroll
            for (int k2 = 0; k2 < 4; k2++)
                ld_raw(t0 + w + ((i + k2) << 4), b, lane, ua[k2], ub[k2]);
            #pragma unroll
            for (int k2 = 0; k2 < 4; k2++) s_upd(s, 1.0f, ua[k2], ub[k2]);
        }
        #pragma unroll
        for (int d = 0; d < 16; d++) red[w][(lane << 4) + d] = s[d];
        __syncthreads();
        float tot = 0.f;
        #pragma unroll
        for (int ww = 0; ww < 16; ww++) tot += red[ww][tid];
        vsm[(tid >> 4) * 17 + (tid & 15)] = tanhf(tot * (1.0f / 32.0f));
        __syncthreads();
        #pragma unroll
        for (int d = 0; d < 16; d++) v[d] = vsm[lane * 17 + d];
        __syncthreads();
    }

    // ---- 3 routing iterations (last produces output) ----
    #pragma unroll 1
    for (int it = 0; it < 3; it++) {
        float s[16];
        #pragma unroll
        for (int d = 0; d < 16; d++) s[d] = 0.f;
        #pragma unroll
        for (int i = 0; i < NT; i += 4) {
            uint4 ua[4], ub[4];
            #pragma unroll
            for (int k2 = 0; k2 < 4; k2++)
                ld_raw(t0 + w + ((i + k2) << 4), b, lane, ua[k2], ub[k2]);

            float e[4], Z[4];
            #pragma unroll
            for (int k2 = 0; k2 < 4; k2++) {
                float bt = beta[i + k2] + dot_raw(v, ua[k2], ub[k2]);
                beta[i + k2] = bt;
                e[k2] = __expf(bt);     // no max-subtract: |beta| small
                Z[k2] = e[k2];
            }
            #pragma unroll
            for (int off = 16; off > 0; off >>= 1) {
                #pragma unroll
                for (int k2 = 0; k2 < 4; k2++)
                    Z[k2] += __shfl_xor_sync(0xffffffffu, Z[k2], off);
            }
            #pragma unroll
            for (int k2 = 0; k2 < 4; k2++)
                s_upd(s, __fdividef(e[k2], Z[k2]), ua[k2], ub[k2]);
        }
        #pragma unroll
        for (int d = 0; d < 16; d++) red[w][(lane << 4) + d] = s[d];
        __syncthreads();
        float tot = 0.f;
        #pragma unroll
        for (int ww = 0; ww < 16; ww++) tot += red[ww][tid];
        if (it == 2) {
            outm[(b << 9) + tid] = tanhf(tot);
        } else {
            vsm[(tid >> 4) * 17 + (tid & 15)] = tanhf(tot);
            __syncthreads();
            #pragma unroll
            for (int d = 0; d < 16; d++) v[d] = vsm[lane * 17 + d];
            __syncthreads();
        }
    }
}

__global__ __launch_bounds__(512) void k_route(float* __restrict__ out)
{
    __shared__ float red[16][512];
    __shared__ float vsm[32 * 17];
    int m = blockIdx.x >> 6;
    int b = blockIdx.x & 63;
    if      (m == 0) route_body<8 >(b,   0, out,          red, vsm);
    else if (m == 1) route_body<32>(b, 128, out + 32768,  red, vsm);
    else if (m == 2) route_body<16>(b, 640, out + 65536,  red, vsm);
    else             route_body<16>(b, 896, out + 98304,  red, vsm);
}

extern "C" void kernel_launch(void* const* d_in, const int* in_sizes, int n_in,
                              void* d_out, int out_size)
{
    const float* xT = (const float*)d_in[0];
    const float* xA = (const float*)d_in[1];
    const float* xV = (const float*)d_in[2];
    const float* xF = (const float*)d_in[3];
    const float* wT = (const float*)d_in[4];
    const float* wA = (const float*)d_in[5];
    const float* wV = (const float*)d_in[6];
    const float* wF = (const float*)d_in[7];

    // Unconditional (no static guard): idempotent, allocation-free, immediate.
    cudaFuncSetAttribute(k_pri, cudaFuncAttributeMaxDynamicSharedMemorySize,
                         K_PRI_SMEM);

    k_pri  <<<1152, 512, K_PRI_SMEM>>>(xT, xA, xV, xF, wT, wA, wV, wF);
    k_route<<<256, 512>>>((float*)d_out);
}

// round 11
// speedup vs baseline: 3.1481x; 1.0976x over previous
#include <cuda_runtime.h>
#include <cuda_fp16.h>
#include <cuda_bf16.h>

// pri scratch: [t_global (1152)][b (64)][n*16+d (512)] fp16 = 75.5 MB
static __device__ __half g_pri[37748736];

// ---------------------------------------------------------------------------
// Kernel 1: pri = x_t @ W_t via bf16 split MMA. Grid 2304: CTA = (t, nd-half).
// 108KB smem + <=63 regs -> 2 CTAs/SM so one CTA's staging (DRAM) overlaps the
// other's MMA (tensor), raising DRAM duty cycle.
// ---------------------------------------------------------------------------
#define SA 72
#define SB 72
#define SC 264
#define K_PRI_SMEM 110592

__device__ __forceinline__ void mma16816(float* c, const unsigned* a,
                                         unsigned b0, unsigned b1) {
    asm volatile(
        "mma.sync.aligned.m16n8k16.row.col.f32.bf16.bf16.f32 "
        "{%0,%1,%2,%3}, {%4,%5,%6,%7}, {%8,%9}, {%0,%1,%2,%3};"
        : "+f"(c[0]), "+f"(c[1]), "+f"(c[2]), "+f"(c[3])
        : "r"(a[0]), "r"(a[1]), "r"(a[2]), "r"(a[3]), "r"(b0), "r"(b1));
}

__global__ __launch_bounds__(512, 2) void k_pri(
    const float* __restrict__ xT, const float* __restrict__ xA,
    const float* __restrict__ xV, const float* __restrict__ xF,
    const float* __restrict__ wT, const float* __restrict__ wA,
    const float* __restrict__ wV, const float* __restrict__ wF)
{
    extern __shared__ __nv_bfloat16 sm[];
    __nv_bfloat16* Ah = sm;                     // 64 x SA
    __nv_bfloat16* Al = Ah + 64 * SA;
    __nv_bfloat16* Bh = Al + 64 * SA;           // 256 x SB (nd half)
    __nv_bfloat16* Bl = Bh + 256 * SB;
    __half* Cs = reinterpret_cast<__half*>(Bh); // reused after MMA (64 x SC)

    int bid  = blockIdx.x;
    int tg   = bid >> 1;
    int half = bid & 1;
    const float* x; const float* w; int T, t;
    if (tg < 128)      { x = xT; w = wT; T = 128; t = tg;       }
    else if (tg < 640) { x = xA; w = wA; T = 512; t = tg - 128; }
    else if (tg < 896) { x = xV; w = wV; T = 256; t = tg - 640; }
    else               { x = xF; w = wF; T = 256; t = tg - 896; }

    int tid = threadIdx.x;

    // ---- stage x_t -> Ah/Al [b][j] ----
    #pragma unroll
    for (int u = tid; u < 2048; u += 512) {
        int bb = u >> 5, jp = u & 31;
        float2 v2 = *reinterpret_cast<const float2*>(
            x + ((size_t)bb * T + t) * 64 + jp * 2);
        __nv_bfloat16 h0 = __float2bfloat16_rn(v2.x);
        __nv_bfloat16 h1 = __float2bfloat16_rn(v2.y);
        __nv_bfloat162 hh; hh.x = h0; hh.y = h1;
        __nv_bfloat162 ll;
        ll.x = __float2bfloat16_rn(v2.x - __bfloat162float(h0));
        ll.y = __float2bfloat16_rn(v2.y - __bfloat162float(h1));
        *reinterpret_cast<__nv_bfloat162*>(&Ah[bb * SA + jp * 2]) = hh;
        *reinterpret_cast<__nv_bfloat162*>(&Al[bb * SA + jp * 2]) = ll;
    }

    // ---- stage this CTA's half of W_t -> Bh/Bl [nd_local][j] ----
    const float4* w4 = reinterpret_cast<const float4*>(w + (size_t)t * 32768);
    #pragma unroll
    for (int u = tid; u < 2048; u += 512) {
        int d0c = u & 3;            // d-quad
        int jp  = (u >> 2) & 31;    // j-pair
        int nl  = u >> 7;           // local n 0..15
        int nbase = (half * 16 + nl) * 256 + jp * 8 + d0c;
        float4 va = __ldg(w4 + nbase);        // j = 2jp
        float4 vb = __ldg(w4 + nbase + 4);    // j = 2jp+1
        float aa[4] = {va.x, va.y, va.z, va.w};
        float bb[4] = {vb.x, vb.y, vb.z, vb.w};
        #pragma unroll
        for (int q = 0; q < 4; q++) {
            int row = (nl << 4) + d0c * 4 + q;      // local nd 0..255
            __nv_bfloat16 ha = __float2bfloat16_rn(aa[q]);
            __nv_bfloat16 hb = __float2bfloat16_rn(bb[q]);
            __nv_bfloat162 hh; hh.x = ha; hh.y = hb;
            __nv_bfloat162 ll;
            ll.x = __float2bfloat16_rn(aa[q] - __bfloat162float(ha));
            ll.y = __float2bfloat16_rn(bb[q] - __bfloat162float(hb));
            *reinterpret_cast<__nv_bfloat162*>(&Bh[row * SB + jp * 2]) = hh;
            *reinterpret_cast<__nv_bfloat162*>(&Bl[row * SB + jp * 2]) = ll;
        }
    }
    __syncthreads();

    // ---- MMA: warp = (m-half) x (32-nd group) ----
    int lane = tid & 31, wrp = tid >> 5;
    int g  = lane >> 2;
    int tq = lane & 3;
    int mbase  = (wrp & 1) * 32;
    int ndbase = (wrp >> 1) * 32;      // local nd

    float acc[2][4][4];
    #pragma unroll
    for (int mt = 0; mt < 2; mt++)
        #pragma unroll
        for (int nt = 0; nt < 4; nt++)
            #pragma unroll
            for (int q = 0; q < 4; q++) acc[mt][nt][q] = 0.f;

    #pragma unroll
    for (int k0 = 0; k0 < 64; k0 += 16) {
        unsigned ah[2][4], al[2][4];
        #pragma unroll
        for (int mt = 0; mt < 2; mt++) {
            int r0 = mbase + mt * 16 + g;
            int kc = k0 + tq * 2;
            ah[mt][0] = *(const unsigned*)&Ah[r0 * SA + kc];
            ah[mt][1] = *(const unsigned*)&Ah[(r0 + 8) * SA + kc];
            ah[mt][2] = *(const unsigned*)&Ah[r0 * SA + kc + 8];
            ah[mt][3] = *(const unsigned*)&Ah[(r0 + 8) * SA + kc + 8];
            al[mt][0] = *(const unsigned*)&Al[r0 * SA + kc];
            al[mt][1] = *(const unsigned*)&Al[(r0 + 8) * SA + kc];
            al[mt][2] = *(const unsigned*)&Al[r0 * SA + kc + 8];
            al[mt][3] = *(const unsigned*)&Al[(r0 + 8) * SA + kc + 8];
        }
        #pragma unroll
        for (int nt = 0; nt < 4; nt++) {
            int col = ndbase + nt * 8 + g;
            int kc  = k0 + tq * 2;
            unsigned bh0 = *(const unsigned*)&Bh[col * SB + kc];
            unsigned bh1 = *(const unsigned*)&Bh[col * SB + kc + 8];
            unsigned bl0 = *(const unsigned*)&Bl[col * SB + kc];
            unsigned bl1 = *(const unsigned*)&Bl[col * SB + kc + 8];
            #pragma unroll
            for (int mt = 0; mt < 2; mt++) {
                mma16816(acc[mt][nt], ah[mt], bh0, bh1);
                mma16816(acc[mt][nt], ah[mt], bl0, bl1);
                mma16816(acc[mt][nt], al[mt], bh0, bh1);
            }
        }
    }
    __syncthreads();   // B smem no longer needed; reuse as Cs

    #pragma unroll
    for (int mt = 0; mt < 2; mt++)
        #pragma unroll
        for (int nt = 0; nt < 4; nt++) {
            int r0 = mbase + mt * 16 + g;
            int c0 = ndbase + nt * 8 + tq * 2;
            __half2 lo = __floats2half2_rn(acc[mt][nt][0], acc[mt][nt][1]);
            __half2 hi = __floats2half2_rn(acc[mt][nt][2], acc[mt][nt][3]);
            *(__half2*)&Cs[r0 * SC + c0]       = lo;
            *(__half2*)&Cs[(r0 + 8) * SC + c0] = hi;
        }
    __syncthreads();

    // coalesced copy: local nd 256 cols -> g_pri half-offset
    __half* base = g_pri + (size_t)tg * 64 * 512 + half * 256;
    #pragma unroll
    for (int i = tid; i < 2048; i += 512) {
        int bb = i >> 5, off = i & 31;
        *reinterpret_cast<uint4*>(base + bb * 512 + off * 8) =
            *(const uint4*)&Cs[bb * SC + off * 8];
    }
}

// ---------------------------------------------------------------------------
// Kernel 2: fused dynamic routing. One CTA per (m, b); 16 warps; lane = vertex.
// 2-way t-interleave; single unpack per t; interleaved shuffle reductions.
// ---------------------------------------------------------------------------
__device__ __forceinline__ void h8f(uint4 u, float* pf) {
    __half2* h = reinterpret_cast<__half2*>(&u);
    #pragma unroll
    for (int k = 0; k < 4; k++) {
        float2 f = __half22float2(h[k]);
        pf[2 * k] = f.x; pf[2 * k + 1] = f.y;
    }
}

__device__ __forceinline__ void load_pf(int tglob, int b, int lane, float* pf) {
    const __half* pp = g_pri + (((size_t)(tglob * 64 + b)) << 9) + (lane << 4);
    uint4 u0 = __ldg((const uint4*)pp);
    uint4 u1 = __ldg((const uint4*)(pp + 8));
    h8f(u0, pf); h8f(u1, pf + 8);
}

__device__ __forceinline__ float dot16(const float* v, const float* p) {
    float s0 = 0.f, s1 = 0.f, s2 = 0.f, s3 = 0.f;
    #pragma unroll
    for (int d = 0; d < 4; d++) {
        s0 = fmaf(v[d],      p[d],      s0);
        s1 = fmaf(v[d + 4],  p[d + 4],  s1);
        s2 = fmaf(v[d + 8],  p[d + 8],  s2);
        s3 = fmaf(v[d + 12], p[d + 12], s3);
    }
    return (s0 + s1) + (s2 + s3);
}

template<int NT>
__device__ __forceinline__ void route_body(int b, int t0, float* __restrict__ outm,
                                           float (*red)[512], float* vsm)
{
    int tid  = threadIdx.x;
    int w    = tid >> 5;
    int lane = tid & 31;

    float beta[NT];
    #pragma unroll
    for (int i = 0; i < NT; i++) beta[i] = 0.f;
    float v[16];

    // ---- pass 0: uniform routing coefficients (softmax(0) = 1/32) ----
    {
        float s[16];
        #pragma unroll
        for (int d = 0; d < 16; d++) s[d] = 0.f;
        #pragma unroll
        for (int i = 0; i < NT; i += 2) {
            float pa[16], pb[16];
            load_pf(t0 + w + (i << 4), b, lane, pa);
            load_pf(t0 + w + ((i + 1) << 4), b, lane, pb);
            #pragma unroll
            for (int d = 0; d < 16; d++) s[d] += pa[d] + pb[d];
        }
        #pragma unroll
        for (int d = 0; d < 16; d++) red[w][(lane << 4) + d] = s[d];
        __syncthreads();
        float tot = 0.f;
        #pragma unroll
        for (int ww = 0; ww < 16; ww++) tot += red[ww][tid];
        vsm[(tid >> 4) * 17 + (tid & 15)] = tanhf(tot * (1.0f / 32.0f));
        __syncthreads();
        #pragma unroll
        for (int d = 0; d < 16; d++) v[d] = vsm[lane * 17 + d];
        __syncthreads();
    }

    // ---- 3 routing iterations (last produces output) ----
    #pragma unroll 1
    for (int it = 0; it < 3; it++) {
        float s[16];
        #pragma unroll
        for (int d = 0; d < 16; d++) s[d] = 0.f;
        #pragma unroll
        for (int i = 0; i < NT; i += 2) {
            float pa[16], pb[16];
            load_pf(t0 + w + (i << 4), b, lane, pa);
            load_pf(t0 + w + ((i + 1) << 4), b, lane, pb);

            float ba = beta[i]     + dot16(v, pa);
            float bb = beta[i + 1] + dot16(v, pb);
            beta[i] = ba; beta[i + 1] = bb;

            // softmax over 32 lanes, no max-subtract (|beta| small).
            // Two independent butterfly chains pipeline across levels.
            float ea = __expf(ba), eb = __expf(bb);
            float Za = ea, Zb = eb;
            #pragma unroll
            for (int off = 16; off > 0; off >>= 1) {
                Za += __shfl_xor_sync(0xffffffffu, Za, off);
                Zb += __shfl_xor_sync(0xffffffffu, Zb, off);
            }
            float ra = __fdividef(ea, Za);
            float rb = __fdividef(eb, Zb);
            #pragma unroll
            for (int d = 0; d < 16; d++)
                s[d] = fmaf(ra, pa[d], fmaf(rb, pb[d], s[d]));
        }
        #pragma unroll
        for (int d = 0; d < 16; d++) red[w][(lane << 4) + d] = s[d];
        __syncthreads();
        float tot = 0.f;
        #pragma unroll
        for (int ww = 0; ww < 16; ww++) tot += red[ww][tid];
        if (it == 2) {
            outm[(b << 9) + tid] = tanhf(tot);
        } else {
            vsm[(tid >> 4) * 17 + (tid & 15)] = tanhf(tot);
            __syncthreads();
            #pragma unroll
            for (int d = 0; d < 16; d++) v[d] = vsm[lane * 17 + d];
            __syncthreads();
        }
    }
}

__global__ __launch_bounds__(512) void k_route(float* __restrict__ out)
{
    __shared__ float red[16][512];
    __shared__ float vsm[32 * 17];
    int m = blockIdx.x >> 6;
    int b = blockIdx.x & 63;
    if      (m == 0) route_body<8 >(b,   0, out,          red, vsm);
    else if (m == 1) route_body<32>(b, 128, out + 32768,  red, vsm);
    else if (m == 2) route_body<16>(b, 640, out + 65536,  red, vsm);
    else             route_body<16>(b, 896, out + 98304,  red, vsm);
}

extern "C" void kernel_launch(void* const* d_in, const int* in_sizes, int n_in,
                              void* d_out, int out_size)
{
    const float* xT = (const float*)d_in[0];
    const float* xA = (const float*)d_in[1];
    const float* xV = (const float*)d_in[2];
    const float* xF = (const float*)d_in[3];
    const float* wT = (const float*)d_in[4];
    const float* wA = (const float*)d_in[5];
    const float* wV = (const float*)d_in[6];
    const float* wF = (const float*)d_in[7];

    // Unconditional (no static guard): idempotent, allocation-free, immediate.
    cudaFuncSetAttribute(k_pri, cudaFuncAttributeMaxDynamicSharedMemorySize,
                         K_PRI_SMEM);

    k_pri  <<<2304, 512, K_PRI_SMEM>>>(xT, xA, xV, xF, wT, wA, wV, wF);
    k_route<<<256, 512>>>((float*)d_out);
}